// round 5
// baseline (speedup 1.0000x reference)
#include <cuda_runtime.h>
#include <cstdint>

#define BATCH 64
#define HIN   32
#define WIN   32
#define CH    3
#define T_STEPS 2700
#define HID   128
#define PRE_N 32
#define VMAX  256
#define GATES 384
#define IN_DIM 14

// +8*GATES pad: xg prefetch pipeline overshoots by up to 3 steps at the tail
__device__ float g_xg[(size_t)BATCH * T_STEPS * GATES + 8 * GATES];
__device__ float g_hs[(size_t)BATCH * T_STEPS * HID];

__device__ __forceinline__ unsigned long long ffma2(unsigned long long a,
                                                    unsigned long long b,
                                                    unsigned long long c) {
    unsigned long long d;
    asm("fma.rn.f32x2 %0, %1, %2, %3;" : "=l"(d) : "l"(a), "l"(b), "l"(c));
    return d;
}
__device__ __forceinline__ float2 unpack2(unsigned long long v) {
    float2 f;
    asm("mov.b64 {%0, %1}, %2;" : "=f"(f.x), "=f"(f.y) : "l"(v));
    return f;
}
__device__ __forceinline__ float tanh_apx(float x) {
    float y;
    asm("tanh.approx.f32 %0, %1;" : "=f"(y) : "f"(x));
    return y;
}
__device__ __forceinline__ float sigmoid_apx(float x) {
    return fmaf(0.5f, tanh_apx(0.5f * x), 0.5f);
}
__device__ __forceinline__ float sigmoidf_fast(float x) {
    return __fdividef(1.0f, 1.0f + __expf(-x));
}

__global__ void k_dummy(int* p) { if (p) *p = 0; }

// ---------------- zero only the output border ----------------
__global__ void k_zero_border(float4* __restrict__ out4) {
    const int total = BATCH * CH * 124 * 64;
    int stride = gridDim.x * blockDim.x;
    for (int idx = blockIdx.x * blockDim.x + threadIdx.x; idx < total; idx += stride) {
        int q = idx & 63;
        int rest = idx >> 6;
        int p = rest % 124;
        int bc = rest / 124;
        int ih, iw;
        if (p < 32)      { ih = 0;       iw = p; }
        else if (p < 64) { ih = 31;      iw = p - 32; }
        else if (p < 94) { ih = p - 63;  iw = 0; }
        else             { ih = p - 93;  iw = 31; }
        out4[((size_t)(bc * HIN + ih) * WIN + iw) * 64 + q] = make_float4(0.f, 0.f, 0.f, 0.f);
    }
}

// ---------------- gather + pre MLP + input gates (b_hh folded for r,z) ----------------
__global__ __launch_bounds__(256) void k_pre(
    const float* __restrict__ x,
    const float* __restrict__ Wpre,
    const float* __restrict__ bpre,
    const float* __restrict__ Wih,
    const float* __restrict__ bih,
    const float* __restrict__ bhh)
{
    __shared__ float WihT[PRE_N * GATES];
    for (int i = threadIdx.x; i < PRE_N * GATES; i += blockDim.x) {
        int g = i >> 5, p = i & 31;
        WihT[p * GATES + g] = Wih[i];
    }
    __syncthreads();

    int warp = threadIdx.x >> 5, lane = threadIdx.x & 31;
    int row = blockIdx.x * 8 + warp;
    if (row >= BATCH * T_STEPS) return;
    int b = row / T_STEPS;
    int s = row - b * T_STEPS;
    int c  = s % 3;
    int iw = (s / 3) % 30;
    int ih = s / 90;

    float val = 0.f;
    if (lane < IN_DIM) {
        if (lane < 12) {
            int g4 = lane / 3, ch = lane % 3;
            int dy = (g4 == 3) ? 1 : 0;
            int dx = (g4 == 3) ? 0 : g4;
            val = x[(((size_t)(b * CH + ch) * HIN) + (ih + dy)) * WIN + (iw + dx)];
        } else {
            int ch = lane - 12;
            val = (c > ch)
                ? x[(((size_t)(b * CH + ch) * HIN) + (ih + 1)) * WIN + (iw + 1)]
                : -1.0f;
        }
    }

    float acc = bpre[lane];
#pragma unroll
    for (int l = 0; l < IN_DIM; l++)
        acc = fmaf(Wpre[lane * IN_DIM + l], __shfl_sync(0xffffffffu, val, l), acc);
    float pre = sigmoidf_fast(acc);

    float accs[12];
#pragma unroll
    for (int i = 0; i < 12; i++) {
        int g = i * 32 + lane;
        accs[i] = bih[g] + ((i < 8) ? bhh[g] : 0.f);
    }
#pragma unroll
    for (int p = 0; p < PRE_N; p++) {
        float pv = __shfl_sync(0xffffffffu, pre, p);
        const float* wr = &WihT[p * GATES + lane];
#pragma unroll
        for (int i = 0; i < 12; i++)
            accs[i] = fmaf(wr[i * 32], pv, accs[i]);
    }
    float* o = g_xg + (size_t)row * GATES;
#pragma unroll
    for (int i = 0; i < 12; i++) o[i * 32 + lane] = accs[i];
}

// ---------------- sequential GRU ----------------
// 512 threads = 128 h-units x 4 K-slices; depth-3 in-place xg prefetch;
// register demand kept < 128 to avoid the spills that plagued r1-r4.
#define HSKEW 160
__global__ __launch_bounds__(512, 1) void k_rnn(
    const float* __restrict__ Whh,
    const float* __restrict__ bhh)
{
    int b   = blockIdx.x;
    int tid = threadIdx.x;
    int j = tid >> 2;
    int s = tid & 3;

    __shared__ __align__(16) float h_sh[2][HSKEW];

    unsigned long long w[3][16];
#pragma unroll
    for (int g = 0; g < 3; g++) {
        const ulonglong2* p = (const ulonglong2*)(Whh + ((size_t)(g * HID + j)) * HID + 32 * s);
#pragma unroll
        for (int k = 0; k < 8; k++) {
            ulonglong2 q = p[k];
            w[g][2 * k]     = q.x;
            w[g][2 * k + 1] = q.y;
        }
    }
    float bn = bhh[2 * HID + j];

    if (tid < HSKEW) { h_sh[0][tid] = 0.f; h_sh[1][tid] = 0.f; }

    int g0 = (s < 3) ? s : 2;
    const float* xgp = g_xg + (size_t)b * T_STEPS * GATES + g0 * HID + j;
    float x0 = xgp[0];
    float x1 = xgp[GATES];
    float x2 = xgp[2 * GATES];
    const float* xp = xgp + 3 * (size_t)GATES;
    float* hsb = g_hs + (size_t)b * T_STEPS * HID + j;
    float hprev = 0.f;
    int lq = (tid & 31) & ~3;

    // precomputed per-buffer pointers (selected by buf; no per-step address math)
    const ulonglong2* hA = (const ulonglong2*)(&h_sh[0][36 * s]);
    const ulonglong2* hB = (const ulonglong2*)(&h_sh[1][36 * s]);
    float* sA = &h_sh[0][j + ((j >> 5) << 2)];
    float* sB = &h_sh[1][j + ((j >> 5) << 2)];
    __syncthreads();

    int buf = 0;

#define GRU_STEP(X, OFF)                                                       \
    {                                                                          \
        float xgc = (X);                                                       \
        (X) = xp[OFF]; /* reload for t+3: 3-step in-flight distance */         \
        const ulonglong2* h2 = buf ? hB : hA;                                  \
        unsigned long long ar = 0ull, az = 0ull, an = 0ull;                    \
        _Pragma("unroll")                                                      \
        for (int k = 0; k < 8; k++) {                                          \
            ulonglong2 q = h2[k];                                              \
            ar = ffma2(w[0][2 * k],     q.x, ar);                              \
            ar = ffma2(w[0][2 * k + 1], q.y, ar);                              \
            az = ffma2(w[1][2 * k],     q.x, az);                              \
            az = ffma2(w[1][2 * k + 1], q.y, az);                              \
            an = ffma2(w[2][2 * k],     q.x, an);                              \
            an = ffma2(w[2][2 * k + 1], q.y, an);                              \
        }                                                                      \
        float2 p;                                                              \
        p = unpack2(ar); float hr = p.x + p.y; if (s == 0) hr += xgc;          \
        p = unpack2(az); float hz = p.x + p.y; if (s == 1) hz += xgc;          \
        p = unpack2(an); float hn = p.x + p.y; if (s == 3) hn += bn;           \
        float xn = __shfl_sync(0xffffffffu, xgc, lq | 2);                      \
        hr += __shfl_xor_sync(0xffffffffu, hr, 1);                             \
        hr += __shfl_xor_sync(0xffffffffu, hr, 2);                             \
        hz += __shfl_xor_sync(0xffffffffu, hz, 1);                             \
        hz += __shfl_xor_sync(0xffffffffu, hz, 2);                             \
        hn += __shfl_xor_sync(0xffffffffu, hn, 1);                             \
        hn += __shfl_xor_sync(0xffffffffu, hn, 2);                             \
        float r = sigmoid_apx(hr);                                             \
        float z = sigmoid_apx(hz);                                             \
        float n = tanh_apx(fmaf(r, hn, xn));                                   \
        float hnew = fmaf(z, hprev - n, n);                                    \
        hprev = hnew;                                                          \
        buf ^= 1;                                                              \
        if (s == 0) { *(buf ? sB : sA) = hnew; hsb[0] = hnew; }                \
        hsb += HID;                                                            \
        __syncthreads();                                                       \
    }

    for (int t = 0; t < T_STEPS; t += 3) {   // 2700 = 900*3
        GRU_STEP(x0, 0);
        GRU_STEP(x1, GATES);
        GRU_STEP(x2, 2 * GATES);
        xp += 3 * (size_t)GATES;
    }
#undef GRU_STEP
}

// ---------------- output head GEMM + scatter (2-row ILP) ----------------
__global__ __launch_bounds__(VMAX, 1) void k_post(
    const float* __restrict__ Wpost,
    const float* __restrict__ bpost,
    float* __restrict__ out)
{
    int blk = blockIdx.x;
    int b = blk / 10;
    int s0 = (blk % 10) * 270;
    int v = threadIdx.x;

    __shared__ __align__(16) float hs_sh[30 * HID];

    unsigned long long w2[64];
    {
        const ulonglong2* wr = (const ulonglong2*)(Wpost + (size_t)v * HID);
#pragma unroll
        for (int k = 0; k < 32; k++) {
            ulonglong2 q = wr[k];
            w2[2 * k]     = q.x;
            w2[2 * k + 1] = q.y;
        }
    }
    float bias = bpost[v];
    const float* hsb = g_hs + (size_t)b * T_STEPS * HID;

    for (int tile = 0; tile < 9; tile++) {
        int sbase = s0 + tile * 30;
        __syncthreads();
        for (int i = v; i < 30 * HID; i += VMAX)
            hs_sh[i] = hsb[(size_t)sbase * HID + i];
        __syncthreads();

        for (int r = 0; r < 30; r += 2) {
            unsigned long long a0 = 0ull, a1 = 0ull, c0 = 0ull, c1 = 0ull;
            const ulonglong2* h0 = (const ulonglong2*)(hs_sh + r * HID);
            const ulonglong2* h1 = (const ulonglong2*)(hs_sh + (r + 1) * HID);
#pragma unroll
            for (int k = 0; k < 32; k++) {
                ulonglong2 q0 = h0[k];
                ulonglong2 q1 = h1[k];
                a0 = ffma2(w2[2 * k],     q0.x, a0);
                a1 = ffma2(w2[2 * k + 1], q0.y, a1);
                c0 = ffma2(w2[2 * k],     q1.x, c0);
                c1 = ffma2(w2[2 * k + 1], q1.y, c1);
            }
            float2 pa = unpack2(a0), pb = unpack2(a1);
            float o0 = (pa.x + pa.y) + (pb.x + pb.y) + bias;
            pa = unpack2(c0); pb = unpack2(c1);
            float o1 = (pa.x + pa.y) + (pb.x + pb.y) + bias;

#pragma unroll
            for (int u = 0; u < 2; u++) {
                int ss = sbase + r + u;
                int c  = ss % 3;
                int iw = (ss / 3) % 30;
                int ih = ss / 90;
                size_t idx = ((((size_t)(b * CH + c) * HIN) + (ih + 1)) * WIN + (iw + 1))
                             * (size_t)VMAX + v;
                out[idx] = u ? o1 : o0;
            }
        }
    }
}

extern "C" void kernel_launch(void* const* d_in, const int* in_sizes, int n_in,
                              void* d_out, int out_size) {
    const float* x      = (const float*)d_in[0];
    const float* W_pre  = (const float*)d_in[1];
    const float* b_pre  = (const float*)d_in[2];
    const float* W_ih   = (const float*)d_in[3];
    const float* b_ih   = (const float*)d_in[4];
    const float* W_hh   = (const float*)d_in[5];
    const float* b_hh   = (const float*)d_in[6];
    const float* W_post = (const float*)d_in[7];
    const float* b_post = (const float*)d_in[8];
    float* out = (float*)d_out;

    k_dummy<<<1, 32>>>(nullptr);
    k_zero_border<<<2976, 512>>>((float4*)out);
    k_pre<<<(BATCH * T_STEPS) / 8, 256>>>(x, W_pre, b_pre, W_ih, b_ih, b_hh);
    k_rnn<<<BATCH, 512>>>(W_hh, b_hh);
    k_post<<<BATCH * 10, VMAX>>>(W_post, b_post, out);
}